// round 12
// baseline (speedup 1.0000x reference)
#include <cuda_runtime.h>
#include <cstdint>

#define BB 1024
#define TT 2048
#define DD 16
#define UU 4
#define HH 128
#define MM 8
#define NT 256
#define PIT 24          // sIN/sH1/sH2 row pitch (floats); cols 0-7 used (tf32 hi)
#define PPIT 10         // sPart row pitch

typedef unsigned long long u64;

__device__ __forceinline__ uint32_t tf32r(float v) {
    uint32_t r; asm("cvt.rna.tf32.f32 %0, %1;" : "=r"(r) : "f"(v)); return r;
}
__device__ __forceinline__ void split(float w, uint32_t& hi, uint32_t& lo) {
    hi = tf32r(w);
    lo = tf32r(w - __uint_as_float(hi));
}
__device__ __forceinline__ float tanh_fast(float x) {
    float y; asm("tanh.approx.f32 %0, %1;" : "=f"(y) : "f"(x)); return y;
}
__device__ __forceinline__ void mma8(float* d, uint4 a, uint32_t b0, uint32_t b1) {
    asm volatile(
        "mma.sync.aligned.m16n8k8.row.col.f32.tf32.tf32.f32 "
        "{%0,%1,%2,%3}, {%4,%5,%6,%7}, {%8,%9}, {%0,%1,%2,%3};"
        : "+f"(d[0]), "+f"(d[1]), "+f"(d[2]), "+f"(d[3])
        : "r"(a.x), "r"(a.y), "r"(a.z), "r"(a.w), "r"(b0), "r"(b1));
}
__device__ __forceinline__ u64 pku(uint32_t lo, uint32_t hi) {
    return ((u64)hi << 32) | (u64)lo;
}

__global__ void __launch_bounds__(NT, 1)
gnsde_kernel(const float* __restrict__ carry,
             const float* __restrict__ x,
             const float* __restrict__ noise,
             const float* __restrict__ W0,
             const float* __restrict__ b0,
             const float* __restrict__ W1,
             const float* __restrict__ b1,
             const float* __restrict__ W2,
             const float* __restrict__ b2,
             float* __restrict__ out)
{
    __shared__ __align__(16) float sIN[32 * PIT];    // rows k: 0-15 y, 16-19 x, 20-31 zero
    __shared__ __align__(16) float sH1[HH * PIT];
    __shared__ __align__(16) float sH2[HH * PIT];
    __shared__ __align__(16) float sPart[8 * 16 * PPIT];

    const int tid  = threadIdx.x;
    const int wid  = tid >> 5;
    const int lane = tid & 31;
    const int g    = lane >> 2;      // groupID
    const int tg   = lane & 3;       // threadID_in_group
    const int b0r  = blockIdx.x * MM;

    const int r0 = wid * 16 + g;     // A-fragment rows (j / d)
    const int r1 = r0 + 8;

    // ---- persistent weight fragments (2-term: hi + lo of A) ----
    uint4 A1h[16], A1l[16];
#pragma unroll
    for (int c = 0; c < 16; ++c) {
        int k0 = 8 * c + tg, k1 = k0 + 4;
        split(W1[k0 * HH + r0], A1h[c].x, A1l[c].x);
        split(W1[k0 * HH + r1], A1h[c].y, A1l[c].y);
        split(W1[k1 * HH + r0], A1h[c].z, A1l[c].z);
        split(W1[k1 * HH + r1], A1h[c].w, A1l[c].w);
    }
    uint4 A0h[4], A0l[4];
#pragma unroll
    for (int c = 0; c < 4; ++c) {
        int k0 = 8 * c + tg, k1 = k0 + 4;
        float v0 = (k0 < DD + UU) ? W0[k0 * HH + r0] : 0.0f;
        float v1 = (k0 < DD + UU) ? W0[k0 * HH + r1] : 0.0f;
        float v2 = (k1 < DD + UU) ? W0[k1 * HH + r0] : 0.0f;
        float v3 = (k1 < DD + UU) ? W0[k1 * HH + r1] : 0.0f;
        split(v0, A0h[c].x, A0l[c].x);
        split(v1, A0h[c].y, A0l[c].y);
        split(v2, A0h[c].z, A0l[c].z);
        split(v3, A0h[c].w, A0l[c].w);
    }
    uint4 A2h[2], A2l[2];
#pragma unroll
    for (int i = 0; i < 2; ++i) {
        int c = 2 * wid + i;
        int k0 = 8 * c + tg, k1 = k0 + 4;
        split(W2[k0 * DD + g],     A2h[i].x, A2l[i].x);
        split(W2[k0 * DD + g + 8], A2h[i].y, A2l[i].y);
        split(W2[k1 * DD + g],     A2h[i].z, A2l[i].z);
        split(W2[k1 * DD + g + 8], A2h[i].w, A2l[i].w);
    }
    const float b0a = b0[r0], b0b = b0[r1];
    const float b1a = b1[r0], b1b = b1[r1];

    // reduce-phase identity (tid < 128): m = tid>>4, d = tid&15
    const int mR = tid >> 4;
    const int dR = tid & 15;
    const float b2v = b2[dR];
    float yreg = 0.0f;

    // ---- init shared ----
    for (int i = tid; i < 32 * PIT; i += NT) sIN[i] = 0.0f;
    __syncthreads();
    uint32_t* sINu = (uint32_t*)sIN;
    uint32_t* sH1u = (uint32_t*)sH1;
    uint32_t* sH2u = (uint32_t*)sH2;
    if (tid < 128) {
        yreg = carry[(size_t)(b0r + mR) * DD + dR];
        sINu[dR * PIT + mR] = tf32r(yreg);
    }
    if (tid >= 128 && tid < 128 + MM) {
        int m = tid & 7;
        float4 xv = *(const float4*)&x[((size_t)(b0r + m) * TT) * UU];
        float xa[4] = {xv.x, xv.y, xv.z, xv.w};
#pragma unroll
        for (int u = 0; u < 4; ++u)
            sINu[(DD + u) * PIT + m] = tf32r(xa[u]);
    }

    const float alpha = 0.1f;
    const float onema = 0.9f;
    const float sqa   = 0.31622776601683794f;

    for (int t = 0; t < TT; ++t) {
        // ---- prefetch globals ----
        float nz = 0.0f;
        if (tid < 128) nz = noise[((size_t)(b0r + mR) * TT + t) * DD + dR];
        float4 xn = make_float4(0.f, 0.f, 0.f, 0.f);
        const bool xp = (tid >= 128 && tid < 128 + MM) && (t + 1 < TT);
        if (xp) xn = *(const float4*)&x[((size_t)(b0r + (tid & 7)) * TT + (t + 1)) * UU];

        __syncthreads();   // (1) y/x writes of prev step -> L0 reads

        // ===== layer 0: 2-term TF32, split chains (P0/P1/Q0/Q1) =====
        {
            float P0[4] = {0, 0, 0, 0}, Q0[4] = {0, 0, 0, 0};
            float P1[4] = {0, 0, 0, 0}, Q1[4] = {0, 0, 0, 0};
#pragma unroll
            for (int c2 = 0; c2 < 2; ++c2) {
                int cA = 2 * c2, cB = 2 * c2 + 1;
                int rA0 = 8 * cA + tg, rA1 = rA0 + 4;
                int rB0 = 8 * cB + tg, rB1 = rB0 + 4;
                uint32_t a0 = sINu[rA0 * PIT + g];
                uint32_t a1 = sINu[rA1 * PIT + g];
                uint32_t bb0 = sINu[rB0 * PIT + g];
                uint32_t bb1 = sINu[rB1 * PIT + g];
                mma8(P0, A0h[cA], a0, a1);
                mma8(Q0, A0l[cA], a0, a1);
                mma8(P1, A0h[cB], bb0, bb1);
                mma8(Q1, A0l[cB], bb0, bb1);
            }
            float h0 = tanh_fast((P0[0] + P1[0]) + (Q0[0] + Q1[0]) + b0a);
            float h1 = tanh_fast((P0[1] + P1[1]) + (Q0[1] + Q1[1]) + b0a);
            float h2 = tanh_fast((P0[2] + P1[2]) + (Q0[2] + Q1[2]) + b0b);
            float h3 = tanh_fast((P0[3] + P1[3]) + (Q0[3] + Q1[3]) + b0b);
            *(u64*)&sH1u[r0 * PIT + 2 * tg] = pku(tf32r(h0), tf32r(h1));
            *(u64*)&sH1u[r1 * PIT + 2 * tg] = pku(tf32r(h2), tf32r(h3));
        }
        __syncthreads();   // (2)

        // ===== layer 1: K=128, 16 chunks, 2-term TF32, split chains =====
        {
            float P0[4] = {0, 0, 0, 0}, Q0[4] = {0, 0, 0, 0};
            float P1[4] = {0, 0, 0, 0}, Q1[4] = {0, 0, 0, 0};
#pragma unroll
            for (int c2 = 0; c2 < 8; ++c2) {
                int cA = 2 * c2, cB = 2 * c2 + 1;
                int rA0 = 8 * cA + tg, rA1 = rA0 + 4;
                int rB0 = 8 * cB + tg, rB1 = rB0 + 4;
                uint32_t a0 = sH1u[rA0 * PIT + g];
                uint32_t a1 = sH1u[rA1 * PIT + g];
                uint32_t bb0 = sH1u[rB0 * PIT + g];
                uint32_t bb1 = sH1u[rB1 * PIT + g];
                mma8(P0, A1h[cA], a0, a1);
                mma8(Q0, A1l[cA], a0, a1);
                mma8(P1, A1h[cB], bb0, bb1);
                mma8(Q1, A1l[cB], bb0, bb1);
            }
            float h0 = tanh_fast((P0[0] + P1[0]) + (Q0[0] + Q1[0]) + b1a);
            float h1 = tanh_fast((P0[1] + P1[1]) + (Q0[1] + Q1[1]) + b1a);
            float h2 = tanh_fast((P0[2] + P1[2]) + (Q0[2] + Q1[2]) + b1b);
            float h3 = tanh_fast((P0[3] + P1[3]) + (Q0[3] + Q1[3]) + b1b);
            *(u64*)&sH2u[r0 * PIT + 2 * tg] = pku(tf32r(h0), tf32r(h1));
            *(u64*)&sH2u[r1 * PIT + 2 * tg] = pku(tf32r(h2), tf32r(h3));
        }
        __syncthreads();   // (3)

        // ===== layer 2: k-split across warps (chunks 2w, 2w+1), 2-term =====
        {
            float P0[4] = {0, 0, 0, 0}, Q0[4] = {0, 0, 0, 0};
            float P1[4] = {0, 0, 0, 0}, Q1[4] = {0, 0, 0, 0};
            {
                int cA = 2 * wid, cB = 2 * wid + 1;
                int rA0 = 8 * cA + tg, rA1 = rA0 + 4;
                int rB0 = 8 * cB + tg, rB1 = rB0 + 4;
                uint32_t a0 = sH2u[rA0 * PIT + g];
                uint32_t a1 = sH2u[rA1 * PIT + g];
                uint32_t bb0 = sH2u[rB0 * PIT + g];
                uint32_t bb1 = sH2u[rB1 * PIT + g];
                mma8(P0, A2h[0], a0, a1);
                mma8(Q0, A2l[0], a0, a1);
                mma8(P1, A2h[1], bb0, bb1);
                mma8(Q1, A2l[1], bb0, bb1);
            }
            float d0 = (P0[0] + P1[0]) + (Q0[0] + Q1[0]);
            float d1 = (P0[1] + P1[1]) + (Q0[1] + Q1[1]);
            float d2 = (P0[2] + P1[2]) + (Q0[2] + Q1[2]);
            float d3 = (P0[3] + P1[3]) + (Q0[3] + Q1[3]);
            *(float2*)&sPart[wid * 160 + g * PPIT + 2 * tg]       = make_float2(d0, d1);
            *(float2*)&sPart[wid * 160 + (g + 8) * PPIT + 2 * tg] = make_float2(d2, d3);
        }
        __syncthreads();   // (4)

        // ===== reduce + gate + outputs: tid<128 = (mR, dR) =====
        if (tid < 128) {
            float s = 0.0f;
#pragma unroll
            for (int w = 0; w < 8; ++w) s += sPart[w * 160 + dR * PPIT + mR];
            float mt = s + b2v;
            float mu = onema * yreg + alpha * mt;
            float yn = mu + sqa * nz;
            size_t base = ((size_t)(b0r + mR) * TT + t) * DD + dR;
            out[base]                        = yn;
            out[base + (size_t)BB * TT * DD] = mt;
            out[base + 2ull * BB * TT * DD]  = mu;
            yreg = yn;
            sINu[dR * PIT + mR] = tf32r(yn);
        } else if (xp) {
            int m = tid & 7;
            float xa[4] = {xn.x, xn.y, xn.z, xn.w};
#pragma unroll
            for (int u = 0; u < 4; ++u)
                sINu[(DD + u) * PIT + m] = tf32r(xa[u]);
        }
    }
}

extern "C" void kernel_launch(void* const* d_in, const int* in_sizes, int n_in,
                              void* d_out, int out_size) {
    const float* carry = (const float*)d_in[0];
    const float* x     = (const float*)d_in[1];
    const float* noise = (const float*)d_in[2];
    const float* W0    = (const float*)d_in[3];
    const float* b0    = (const float*)d_in[4];
    const float* W1    = (const float*)d_in[5];
    const float* b1    = (const float*)d_in[6];
    const float* W2    = (const float*)d_in[7];
    const float* b2    = (const float*)d_in[8];
    float* out = (float*)d_out;

    gnsde_kernel<<<BB / MM, NT>>>(carry, x, noise, W0, b0, W1, b1, W2, b2, out);
}

// round 13
// speedup vs baseline: 1.0354x; 1.0354x over previous
#include <cuda_runtime.h>
#include <cstdint>

#define BB 1024
#define TT 2048
#define DD 16
#define UU 4
#define HH 128
#define MM 8
#define NT 256
#define PIT 24          // sIN/sH1/sH2 row pitch (floats)
#define PPIT 10         // sPart row pitch

typedef unsigned long long u64;

__device__ __forceinline__ uint32_t tf32r(float v) {
    uint32_t r; asm("cvt.rna.tf32.f32 %0, %1;" : "=r"(r) : "f"(v)); return r;
}
__device__ __forceinline__ void split(float w, uint32_t& hi, uint32_t& lo) {
    hi = tf32r(w);
    lo = tf32r(w - __uint_as_float(hi));
}
__device__ __forceinline__ float tanh_fast(float x) {
    float y; asm("tanh.approx.f32 %0, %1;" : "=f"(y) : "f"(x)); return y;
}
__device__ __forceinline__ void mma8(float* d, uint4 a, uint32_t b0, uint32_t b1) {
    asm volatile(
        "mma.sync.aligned.m16n8k8.row.col.f32.tf32.tf32.f32 "
        "{%0,%1,%2,%3}, {%4,%5,%6,%7}, {%8,%9}, {%0,%1,%2,%3};"
        : "+f"(d[0]), "+f"(d[1]), "+f"(d[2]), "+f"(d[3])
        : "r"(a.x), "r"(a.y), "r"(a.z), "r"(a.w), "r"(b0), "r"(b1));
}
__device__ __forceinline__ u64 pku(uint32_t lo, uint32_t hi) {
    return ((u64)hi << 32) | (u64)lo;
}

__global__ void __launch_bounds__(NT, 1)
gnsde_kernel(const float* __restrict__ carry,
             const float* __restrict__ x,
             const float* __restrict__ noise,
             const float* __restrict__ W0,
             const float* __restrict__ b0,
             const float* __restrict__ W1,
             const float* __restrict__ b1,
             const float* __restrict__ W2,
             const float* __restrict__ b2,
             float* __restrict__ out)
{
    __shared__ __align__(16) float sIN[DD * PIT];    // y rows only (tf32 hi in cols 0-7)
    __shared__ __align__(16) float sX[MM * 4];       // x_t, fp32, [m][u]
    __shared__ __align__(16) float sH1[HH * PIT];
    __shared__ __align__(16) float sH2[HH * PIT];
    __shared__ __align__(16) float sPart[8 * 16 * PPIT];

    const int tid  = threadIdx.x;
    const int wid  = tid >> 5;
    const int lane = tid & 31;
    const int g    = lane >> 2;      // groupID
    const int tg   = lane & 3;       // threadID_in_group
    const int b0r  = blockIdx.x * MM;

    const int r0 = wid * 16 + g;     // A-fragment rows (j / d)
    const int r1 = r0 + 8;

    // ---- persistent weight fragments (2-term: hi + lo of A) ----
    uint4 A1h[16], A1l[16];
#pragma unroll
    for (int c = 0; c < 16; ++c) {
        int k0 = 8 * c + tg, k1 = k0 + 4;
        split(W1[k0 * HH + r0], A1h[c].x, A1l[c].x);
        split(W1[k0 * HH + r1], A1h[c].y, A1l[c].y);
        split(W1[k1 * HH + r0], A1h[c].z, A1l[c].z);
        split(W1[k1 * HH + r1], A1h[c].w, A1l[c].w);
    }
    uint4 A0h[2], A0l[2];
#pragma unroll
    for (int c = 0; c < 2; ++c) {    // y rows only: k 0..15
        int k0 = 8 * c + tg, k1 = k0 + 4;
        split(W0[k0 * HH + r0], A0h[c].x, A0l[c].x);
        split(W0[k0 * HH + r1], A0h[c].y, A0l[c].y);
        split(W0[k1 * HH + r0], A0h[c].z, A0l[c].z);
        split(W0[k1 * HH + r1], A0h[c].w, A0l[c].w);
    }
    float w0xA[UU], w0xB[UU];        // W0 x-rows, fp32 exact
#pragma unroll
    for (int u = 0; u < UU; ++u) {
        w0xA[u] = W0[(DD + u) * HH + r0];
        w0xB[u] = W0[(DD + u) * HH + r1];
    }
    uint4 A2h[2], A2l[2];
#pragma unroll
    for (int i = 0; i < 2; ++i) {
        int c = 2 * wid + i;
        int k0 = 8 * c + tg, k1 = k0 + 4;
        split(W2[k0 * DD + g],     A2h[i].x, A2l[i].x);
        split(W2[k0 * DD + g + 8], A2h[i].y, A2l[i].y);
        split(W2[k1 * DD + g],     A2h[i].z, A2l[i].z);
        split(W2[k1 * DD + g + 8], A2h[i].w, A2l[i].w);
    }
    const float b0a = b0[r0], b0b = b0[r1];
    const float b1a = b1[r0], b1b = b1[r1];

    // reduce-phase identity (tid < 128): m = tid>>4, d = tid&15
    const int mR = tid >> 4;
    const int dR = tid & 15;
    const float b2v = b2[dR];
    float yreg = 0.0f;

    uint32_t* sINu = (uint32_t*)sIN;
    uint32_t* sH1u = (uint32_t*)sH1;
    uint32_t* sH2u = (uint32_t*)sH2;
    if (tid < 128) {
        yreg = carry[(size_t)(b0r + mR) * DD + dR];
        sINu[dR * PIT + mR] = tf32r(yreg);
    }
    if (tid >= 128 && tid < 128 + MM) {
        int m = tid & 7;
        float4 xv = *(const float4*)&x[((size_t)(b0r + m) * TT) * UU];
        *(float4*)&sX[m * 4] = xv;
    }

    const float alpha = 0.1f;
    const float onema = 0.9f;
    const float sqa   = 0.31622776601683794f;

    for (int t = 0; t < TT; ++t) {
        // ---- prefetch globals ----
        float nz = 0.0f;
        if (tid < 128) nz = noise[((size_t)(b0r + mR) * TT + t) * DD + dR];
        float4 xn = make_float4(0.f, 0.f, 0.f, 0.f);
        const bool xp = (tid >= 128 && tid < 128 + MM) && (t + 1 < TT);
        if (xp) xn = *(const float4*)&x[((size_t)(b0r + (tid & 7)) * TT + (t + 1)) * UU];

        __syncthreads();   // (1) y/x writes of prev step -> L0 reads

        // ===== layer 0: K=16 MMA over y + fp32 scalar x-fold =====
        {
            float P[4] = {0, 0, 0, 0}, Q[4] = {0, 0, 0, 0};
#pragma unroll
            for (int c = 0; c < 2; ++c) {
                int rA = 8 * c + tg, rB = rA + 4;
                uint32_t bh0 = sINu[rA * PIT + g];
                uint32_t bh1 = sINu[rB * PIT + g];
                mma8(P, A0h[c], bh0, bh1);
                mma8(Q, A0l[c], bh0, bh1);
            }
            float4 xa = *(const float4*)&sX[(2 * tg) * 4];
            float4 xb = *(const float4*)&sX[(2 * tg + 1) * 4];
            float s0 = w0xA[0] * xa.x + w0xA[1] * xa.y + w0xA[2] * xa.z + w0xA[3] * xa.w;
            float s1 = w0xA[0] * xb.x + w0xA[1] * xb.y + w0xA[2] * xb.z + w0xA[3] * xb.w;
            float s2 = w0xB[0] * xa.x + w0xB[1] * xa.y + w0xB[2] * xa.z + w0xB[3] * xa.w;
            float s3 = w0xB[0] * xb.x + w0xB[1] * xb.y + w0xB[2] * xb.z + w0xB[3] * xb.w;
            float h0 = tanh_fast(P[0] + Q[0] + s0 + b0a);
            float h1 = tanh_fast(P[1] + Q[1] + s1 + b0a);
            float h2 = tanh_fast(P[2] + Q[2] + s2 + b0b);
            float h3 = tanh_fast(P[3] + Q[3] + s3 + b0b);
            *(u64*)&sH1u[r0 * PIT + 2 * tg] = pku(tf32r(h0), tf32r(h1));
            *(u64*)&sH1u[r1 * PIT + 2 * tg] = pku(tf32r(h2), tf32r(h3));
        }
        __syncthreads();   // (2)

        // ===== layer 1: K=128, 16 chunks, 2-term TF32 =====
        {
            float P[4] = {0, 0, 0, 0}, Q[4] = {0, 0, 0, 0};
#pragma unroll
            for (int c = 0; c < 16; ++c) {
                int rA = 8 * c + tg, rB = rA + 4;
                uint32_t bh0 = sH1u[rA * PIT + g];
                uint32_t bh1 = sH1u[rB * PIT + g];
                mma8(P, A1h[c], bh0, bh1);
                mma8(Q, A1l[c], bh0, bh1);
            }
            float h0 = tanh_fast(P[0] + Q[0] + b1a);
            float h1 = tanh_fast(P[1] + Q[1] + b1a);
            float h2 = tanh_fast(P[2] + Q[2] + b1b);
            float h3 = tanh_fast(P[3] + Q[3] + b1b);
            *(u64*)&sH2u[r0 * PIT + 2 * tg] = pku(tf32r(h0), tf32r(h1));
            *(u64*)&sH2u[r1 * PIT + 2 * tg] = pku(tf32r(h2), tf32r(h3));
        }
        __syncthreads();   // (3)

        // ===== layer 2: k-split across warps (chunks 2w, 2w+1), 2-term =====
        {
            float P[4] = {0, 0, 0, 0}, Q[4] = {0, 0, 0, 0};
#pragma unroll
            for (int i = 0; i < 2; ++i) {
                int rA = 8 * (2 * wid + i) + tg, rB = rA + 4;
                uint32_t bh0 = sH2u[rA * PIT + g];
                uint32_t bh1 = sH2u[rB * PIT + g];
                mma8(P, A2h[i], bh0, bh1);
                mma8(Q, A2l[i], bh0, bh1);
            }
            float d0 = P[0] + Q[0];
            float d1 = P[1] + Q[1];
            float d2 = P[2] + Q[2];
            float d3 = P[3] + Q[3];
            *(float2*)&sPart[wid * 160 + g * PPIT + 2 * tg]       = make_float2(d0, d1);
            *(float2*)&sPart[wid * 160 + (g + 8) * PPIT + 2 * tg] = make_float2(d2, d3);
        }

        // (4) asymmetric: warps 0-3 sync (they reduce); warps 4-7 arrive and move on
        if (wid < 4) {
            asm volatile("bar.sync 1, %0;" :: "n"(NT) : "memory");
            // ===== reduce + gate + outputs: tid<128 = (mR, dR) =====
            float s = 0.0f;
#pragma unroll
            for (int w = 0; w < 8; ++w) s += sPart[w * 160 + dR * PPIT + mR];
            float mt = s + b2v;
            float mu = onema * yreg + alpha * mt;
            float yn = mu + sqa * nz;
            size_t base = ((size_t)(b0r + mR) * TT + t) * DD + dR;
            out[base]                        = yn;
            out[base + (size_t)BB * TT * DD] = mt;
            out[base + 2ull * BB * TT * DD]  = mu;
            yreg = yn;
            sINu[dR * PIT + mR] = tf32r(yn);
        } else {
            asm volatile("bar.arrive 1, %0;" :: "n"(NT) : "memory");
            if (xp) {
                int m = tid & 7;
                *(float4*)&sX[m * 4] = xn;   // x(t+1), fp32; ordered by bar (1)
            }
        }
    }
}

extern "C" void kernel_launch(void* const* d_in, const int* in_sizes, int n_in,
                              void* d_out, int out_size) {
    const float* carry = (const float*)d_in[0];
    const float* x     = (const float*)d_in[1];
    const float* noise = (const float*)d_in[2];
    const float* W0    = (const float*)d_in[3];
    const float* b0    = (const float*)d_in[4];
    const float* W1    = (const float*)d_in[5];
    const float* b1    = (const float*)d_in[6];
    const float* W2    = (const float*)d_in[7];
    const float* b2    = (const float*)d_in[8];
    float* out = (float*)d_out;

    gnsde_kernel<<<BB / MM, NT>>>(carry, x, noise, W0, b0, W1, b1, W2, b2, out);
}